// round 14
// baseline (speedup 1.0000x reference)
#include <cuda_runtime.h>

#define HPF 32
#define NBLK 20
#define HID 640
#define BATCHN 128
#define SEQ 512
#define INSZ 16
#define NB2CNT 784          // CTAs running 2 batches (units 0..1567)
#define NCTA 1776           // 784*2 + 992*1 = 2560 units; 12 warps/SM, one wave

// ---- packed fp32x2 helpers (sm_103a dual fp32) ----
__device__ __forceinline__ unsigned long long pk2(float a, float b) {
    unsigned long long r;
    asm("mov.b64 %0, {%1, %2};" : "=l"(r) : "f"(a), "f"(b));
    return r;
}
__device__ __forceinline__ float2 upk2(unsigned long long v) {
    float2 f;
    asm("mov.b64 {%0, %1}, %2;" : "=f"(f.x), "=f"(f.y) : "l"(v));
    return f;
}
__device__ __forceinline__ void fma2(unsigned long long& d,
                                     unsigned long long a, unsigned long long b) {
    asm("fma.rn.f32x2 %0, %1, %2, %0;" : "+l"(d) : "l"(a), "l"(b));
}
// 3-operand form: d = a*b + c (seeds the accumulator with bias, no init cost)
__device__ __forceinline__ unsigned long long fma2s(unsigned long long a,
                                                    unsigned long long b,
                                                    unsigned long long c) {
    unsigned long long d;
    asm("fma.rn.f32x2 %0, %1, %2, %3;" : "=l"(d) : "l"(a), "l"(b), "l"(c));
    return d;
}
__device__ __forceinline__ float tanhapx(float x) {
    float r;
    asm("tanh.approx.f32 %0, %1;" : "=f"(r) : "f"(x));
    return r;
}

struct Params {
    unsigned long long vr[4][16];   // V columns, packed over m-pairs
    unsigned long long uab[4];      // (ua, ub) packed   -> x-term as 17th matvec pair
    unsigned long long bias2[4];    // (bias, 0) packed  -> seeds the accumulator
    int fa, fb, col;
};

__device__ __forceinline__ void load_params(
    Params& P, int j, int lane,
    const float* __restrict__ Vi, const float* __restrict__ Vf,
    const float* __restrict__ Vc, const float* __restrict__ Vo,
    const float* __restrict__ Ui, const float* __restrict__ Uf,
    const float* __restrict__ Uc, const float* __restrict__ Uo,
    const float* __restrict__ bi, const float* __restrict__ bf,
    const float* __restrict__ bc, const float* __restrict__ bo)
{
    const float* Vg[4] = {Vi, Vf, Vc, Vo};
    const float* Ug[4] = {Ui, Uf, Uc, Uo};
    const float* Bg[4] = {bi, bf, bc, bo};
    const int col = j * HPF + lane;
    P.col = col;
    #pragma unroll
    for (int g = 0; g < 4; ++g) {
        #pragma unroll
        for (int q = 0; q < 16; ++q) {
            const float v0 = __ldg(&Vg[g][(j * HPF + 2 * q)     * HID + col]);
            const float v1 = __ldg(&Vg[g][(j * HPF + 2 * q + 1) * HID + col]);
            P.vr[g][q] = pk2(v0, v1);
        }
    }
    #pragma unroll
    for (int g = 0; g < 4; ++g) {
        float a = 0.0f, bb = 0.0f;
        if (j < 16) a = __ldg(&Ug[g][j * HID + col]);
        if (j == 0) { a += __ldg(&Ug[g][16 * HID + col]); bb = __ldg(&Ug[g][17 * HID + col]); }
        if (j == 2) { a += __ldg(&Ug[g][18 * HID + col]); bb = __ldg(&Ug[g][19 * HID + col]); }
        P.uab[g]   = pk2(a, bb);
        P.bias2[g] = pk2(__ldg(&Bg[g][col]), 0.0f);
    }
    P.fa = (j == 0) ? 0 : ((j == 2) ? 2 : ((j < 16) ? j : 0));
    P.fb = (j == 0) ? 1 : ((j == 2) ? 3 : 0);   // ub==0 when unused
}

// matvec for one batch: 16 h-pairs + x-pair (17th), bias-seeded.
__device__ __forceinline__ void matvec(unsigned long long acc[4],
                                       const Params& P,
                                       const float* __restrict__ hsb,
                                       unsigned long long xp)
{
    {
        const ulonglong2 hp = *reinterpret_cast<const ulonglong2*>(hsb);
        #pragma unroll
        for (int g = 0; g < 4; ++g) {
            acc[g] = fma2s(hp.x, P.vr[g][0], P.bias2[g]);
            fma2(acc[g], hp.y, P.vr[g][1]);
        }
    }
    #pragma unroll
    for (int q4 = 1; q4 < 4; ++q4) {
        const ulonglong2 hp = *reinterpret_cast<const ulonglong2*>(hsb + 8 * q4);
        const ulonglong2 hq = *reinterpret_cast<const ulonglong2*>(hsb + 8 * q4 + 4);
        #pragma unroll
        for (int g = 0; g < 4; ++g) {
            fma2(acc[g], hp.x, P.vr[g][4 * q4]);
            fma2(acc[g], hp.y, P.vr[g][4 * q4 + 1]);
            fma2(acc[g], hq.x, P.vr[g][4 * q4 + 2]);
            fma2(acc[g], hq.y, P.vr[g][4 * q4 + 3]);
        }
    }
    {   // second quarter (q=2,3) of the first 8 + x-term
        const ulonglong2 hq = *reinterpret_cast<const ulonglong2*>(hsb + 4);
        #pragma unroll
        for (int g = 0; g < 4; ++g) {
            fma2(acc[g], hq.x, P.vr[g][2]);
            fma2(acc[g], hq.y, P.vr[g][3]);
            fma2(acc[g], xp,   P.uab[g]);
        }
    }
}

__device__ __forceinline__ void gate_epilogue(
    const unsigned long long acc[4], float& c, float& h)
{
    const float2 pi = upk2(acc[0]);
    const float2 pf = upk2(acc[1]);
    const float2 pc = upk2(acc[2]);
    const float2 po = upk2(acc[3]);
    const float it = fmaf(0.5f, tanhapx(0.5f * (pi.x + pi.y)), 0.5f);
    const float ft = fmaf(0.5f, tanhapx(0.5f * (pf.x + pf.y)), 0.5f);
    const float tg = tanhapx(pc.x + pc.y);
    const float ot = fmaf(0.5f, tanhapx(0.5f * (po.x + po.y)), 0.5f);
    c = fmaf(ft, c, it * tg);
    h = ot * tanhapx(c);
}

__global__ __launch_bounds__(32, 12)
void lstm_fused_kernel(const float* __restrict__ x,
                       const float* __restrict__ Ui, const float* __restrict__ Vi, const float* __restrict__ bi,
                       const float* __restrict__ Uf, const float* __restrict__ Vf, const float* __restrict__ bf,
                       const float* __restrict__ Uc, const float* __restrict__ Vc, const float* __restrict__ bc,
                       const float* __restrict__ Uo, const float* __restrict__ Vo, const float* __restrict__ bo,
                       float* __restrict__ out, long long out_size)
{
    __shared__ __align__(16) float hs0[HPF];
    __shared__ __align__(16) float hs1[HPF];
    __shared__ __align__(16) float2 xs[2][SEQ + 1];

    const int lane = threadIdx.x;
    const int bid  = blockIdx.x;
    const long long hsz = (long long)BATCHN * SEQ * HID;
    const bool tails = (out_size >= hsz + 2LL * BATCHN * HID);

    Params P;

    if (bid < NB2CNT) {
        // ===================== NB=2 path =====================
        const int u0 = 2 * bid;
        const int j  = u0 >> 7;
        const int b0 = u0 & 127;
        load_params(P, j, lane, Vi, Vf, Vc, Vo, Ui, Uf, Uc, Uo, bi, bf, bc, bo);

        const float* xq0 = x + (long long)(b0 + 0) * SEQ * INSZ;
        const float* xq1 = x + (long long)(b0 + 1) * SEQ * INSZ;
        float* outp0 = out + (long long)(b0 + 0) * SEQ * HID + P.col;
        float* outp1 = out + (long long)(b0 + 1) * SEQ * HID + P.col;

        #pragma unroll 4
        for (int i = lane; i < SEQ; i += 32) {
            xs[0][i] = make_float2(__ldg(xq0 + i * INSZ + P.fa), __ldg(xq0 + i * INSZ + P.fb));
            xs[1][i] = make_float2(__ldg(xq1 + i * INSZ + P.fa), __ldg(xq1 + i * INSZ + P.fb));
        }
        if (lane == 0) { xs[0][SEQ] = make_float2(0.f, 0.f); xs[1][SEQ] = make_float2(0.f, 0.f); }

        float h0 = 0.0f, c0 = 0.0f, h1 = 0.0f, c1 = 0.0f;
        hs0[lane] = 0.0f; hs1[lane] = 0.0f;
        __syncwarp();

        unsigned long long acc0[4];
        matvec(acc0, P, hs0, *reinterpret_cast<const unsigned long long*>(&xs[0][0]));

        for (int t = 0; t < SEQ; ++t) {
            // Phase A: matvec1(t) || epilogue0(t)
            unsigned long long acc1[4];
            matvec(acc1, P, hs1, *reinterpret_cast<const unsigned long long*>(&xs[1][t]));
            gate_epilogue(acc0, c0, h0);
            *outp0 = h0; outp0 += HID;
            hs0[lane] = h0;
            __syncwarp();

            // Phase B: matvec0(t+1) || epilogue1(t)
            matvec(acc0, P, hs0, *reinterpret_cast<const unsigned long long*>(&xs[0][t + 1]));
            gate_epilogue(acc1, c1, h1);
            *outp1 = h1; outp1 += HID;
            hs1[lane] = h1;
            __syncwarp();
        }

        if (tails) {
            out[hsz + (long long)(b0 + 0) * HID + P.col] = h0;
            out[hsz + (long long)(b0 + 1) * HID + P.col] = h1;
            out[hsz + (long long)BATCHN * HID + (long long)(b0 + 0) * HID + P.col] = c0;
            out[hsz + (long long)BATCHN * HID + (long long)(b0 + 1) * HID + P.col] = c1;
        }
    } else {
        // ===================== NB=1 path =====================
        const int u  = 2 * NB2CNT + (bid - NB2CNT);    // 1568..2559
        const int j  = u >> 7;
        const int b  = u & 127;
        load_params(P, j, lane, Vi, Vf, Vc, Vo, Ui, Uf, Uc, Uo, bi, bf, bc, bo);

        const float* xq = x + (long long)b * SEQ * INSZ;
        float* outp = out + (long long)b * SEQ * HID + P.col;

        #pragma unroll 4
        for (int i = lane; i < SEQ; i += 32) {
            xs[0][i] = make_float2(__ldg(xq + i * INSZ + P.fa), __ldg(xq + i * INSZ + P.fb));
        }

        float h = 0.0f, c = 0.0f;
        hs0[lane] = 0.0f;
        __syncwarp();

        for (int t = 0; t < SEQ; ++t) {
            unsigned long long acc[4];
            matvec(acc, P, hs0, *reinterpret_cast<const unsigned long long*>(&xs[0][t]));
            gate_epilogue(acc, c, h);
            *outp = h; outp += HID;
            hs0[lane] = h;        // all reads of h(t-1) precede this in program order
            __syncwarp();          // fence before next step's reads
        }

        if (tails) {
            out[hsz + (long long)b * HID + P.col] = h;
            out[hsz + (long long)BATCHN * HID + (long long)b * HID + P.col] = c;
        }
    }
}

extern "C" void kernel_launch(void* const* d_in, const int* in_sizes, int n_in,
                              void* d_out, int out_size)
{
    const float* x  = (const float*)d_in[0];
    const float* Ui = (const float*)d_in[1];
    const float* Vi = (const float*)d_in[2];
    const float* bi = (const float*)d_in[3];
    const float* Uf = (const float*)d_in[4];
    const float* Vf = (const float*)d_in[5];
    const float* bf = (const float*)d_in[6];
    const float* Uc = (const float*)d_in[7];
    const float* Vc = (const float*)d_in[8];
    const float* bc = (const float*)d_in[9];
    const float* Uo = (const float*)d_in[10];
    const float* Vo = (const float*)d_in[11];
    const float* bo = (const float*)d_in[12];
    float* out = (float*)d_out;

    lstm_fused_kernel<<<NCTA, 32>>>(
        x, Ui, Vi, bi, Uf, Vf, bf, Uc, Vc, bc, Uo, Vo, bo,
        out, (long long)out_size);
}

// round 16
// speedup vs baseline: 1.0401x; 1.0401x over previous
#include <cuda_runtime.h>

#define HPF 32
#define NBLK 20
#define HID 640
#define BATCHN 128
#define SEQ 512
#define INSZ 16
#define NUNIT 2560          // 20 j-blocks * 128 batches
#define HALFSEQ 256
#define NCTA (2 * NUNIT)    // first 2560 CTAs: steps [0,256); last 2560: [256,512)

// handoff scratch: per unit 32 h + 32 c, plus a flag (zero-initialized)
__device__ float g_state[NUNIT * 64];
__device__ int   g_flag[NUNIT];

// ---- packed fp32x2 helpers (sm_103a dual fp32) ----
__device__ __forceinline__ unsigned long long pk2(float a, float b) {
    unsigned long long r;
    asm("mov.b64 %0, {%1, %2};" : "=l"(r) : "f"(a), "f"(b));
    return r;
}
__device__ __forceinline__ float2 upk2(unsigned long long v) {
    float2 f;
    asm("mov.b64 {%0, %1}, %2;" : "=f"(f.x), "=f"(f.y) : "l"(v));
    return f;
}
__device__ __forceinline__ void fma2(unsigned long long& d,
                                     unsigned long long a, unsigned long long b) {
    asm("fma.rn.f32x2 %0, %1, %2, %0;" : "+l"(d) : "l"(a), "l"(b));
}
__device__ __forceinline__ unsigned long long fma2s(unsigned long long a,
                                                    unsigned long long b,
                                                    unsigned long long c) {
    unsigned long long d;
    asm("fma.rn.f32x2 %0, %1, %2, %3;" : "=l"(d) : "l"(a), "l"(b), "l"(c));
    return d;
}
__device__ __forceinline__ float tanhapx(float x) {
    float r;
    asm("tanh.approx.f32 %0, %1;" : "=f"(r) : "f"(x));
    return r;
}

struct Params {
    unsigned long long vr[4][16];   // V columns, packed over m-pairs
    unsigned long long uab[4];      // (ua, ub) packed
    unsigned long long bias2[4];    // (bias, 0) packed (accumulator seed)
    int fa, fb, col;
};

__device__ __forceinline__ void load_params(
    Params& P, int j, int lane,
    const float* __restrict__ Vi, const float* __restrict__ Vf,
    const float* __restrict__ Vc, const float* __restrict__ Vo,
    const float* __restrict__ Ui, const float* __restrict__ Uf,
    const float* __restrict__ Uc, const float* __restrict__ Uo,
    const float* __restrict__ bi, const float* __restrict__ bf,
    const float* __restrict__ bc, const float* __restrict__ bo)
{
    const float* Vg[4] = {Vi, Vf, Vc, Vo};
    const float* Ug[4] = {Ui, Uf, Uc, Uo};
    const float* Bg[4] = {bi, bf, bc, bo};
    const int col = j * HPF + lane;
    P.col = col;
    #pragma unroll
    for (int g = 0; g < 4; ++g) {
        #pragma unroll
        for (int q = 0; q < 16; ++q) {
            const float v0 = __ldg(&Vg[g][(j * HPF + 2 * q)     * HID + col]);
            const float v1 = __ldg(&Vg[g][(j * HPF + 2 * q + 1) * HID + col]);
            P.vr[g][q] = pk2(v0, v1);
        }
    }
    #pragma unroll
    for (int g = 0; g < 4; ++g) {
        float a = 0.0f, bb = 0.0f;
        if (j < 16) a = __ldg(&Ug[g][j * HID + col]);
        if (j == 0) { a += __ldg(&Ug[g][16 * HID + col]); bb = __ldg(&Ug[g][17 * HID + col]); }
        if (j == 2) { a += __ldg(&Ug[g][18 * HID + col]); bb = __ldg(&Ug[g][19 * HID + col]); }
        P.uab[g]   = pk2(a, bb);
        P.bias2[g] = pk2(__ldg(&Bg[g][col]), 0.0f);
    }
    P.fa = (j == 0) ? 0 : ((j == 2) ? 2 : ((j < 16) ? j : 0));
    P.fb = (j == 0) ? 1 : ((j == 2) ? 3 : 0);   // ub==0 when unused
}

// matvec: 16 h-pairs + x-pair, bias-seeded (R14-proven)
__device__ __forceinline__ void matvec(unsigned long long acc[4],
                                       const Params& P,
                                       const float* __restrict__ hsb,
                                       unsigned long long xp)
{
    {
        const ulonglong2 hp = *reinterpret_cast<const ulonglong2*>(hsb);
        #pragma unroll
        for (int g = 0; g < 4; ++g) {
            acc[g] = fma2s(hp.x, P.vr[g][0], P.bias2[g]);
            fma2(acc[g], hp.y, P.vr[g][1]);
        }
    }
    #pragma unroll
    for (int q4 = 1; q4 < 4; ++q4) {
        const ulonglong2 hp = *reinterpret_cast<const ulonglong2*>(hsb + 8 * q4);
        const ulonglong2 hq = *reinterpret_cast<const ulonglong2*>(hsb + 8 * q4 + 4);
        #pragma unroll
        for (int g = 0; g < 4; ++g) {
            fma2(acc[g], hp.x, P.vr[g][4 * q4]);
            fma2(acc[g], hp.y, P.vr[g][4 * q4 + 1]);
            fma2(acc[g], hq.x, P.vr[g][4 * q4 + 2]);
            fma2(acc[g], hq.y, P.vr[g][4 * q4 + 3]);
        }
    }
    {
        const ulonglong2 hq = *reinterpret_cast<const ulonglong2*>(hsb + 4);
        #pragma unroll
        for (int g = 0; g < 4; ++g) {
            fma2(acc[g], hq.x, P.vr[g][2]);
            fma2(acc[g], hq.y, P.vr[g][3]);
            fma2(acc[g], xp,   P.uab[g]);
        }
    }
}

__device__ __forceinline__ void gate_epilogue(
    const unsigned long long acc[4], float& c, float& h)
{
    const float2 pi = upk2(acc[0]);
    const float2 pf = upk2(acc[1]);
    const float2 pc = upk2(acc[2]);
    const float2 po = upk2(acc[3]);
    const float it = fmaf(0.5f, tanhapx(0.5f * (pi.x + pi.y)), 0.5f);
    const float ft = fmaf(0.5f, tanhapx(0.5f * (pf.x + pf.y)), 0.5f);
    const float tg = tanhapx(pc.x + pc.y);
    const float ot = fmaf(0.5f, tanhapx(0.5f * (po.x + po.y)), 0.5f);
    c = fmaf(ft, c, it * tg);
    h = ot * tanhapx(c);
}

__global__ __launch_bounds__(32, 12)
void lstm_fused_kernel(const float* __restrict__ x,
                       const float* __restrict__ Ui, const float* __restrict__ Vi, const float* __restrict__ bi,
                       const float* __restrict__ Uf, const float* __restrict__ Vf, const float* __restrict__ bf,
                       const float* __restrict__ Uc, const float* __restrict__ Vc, const float* __restrict__ bc,
                       const float* __restrict__ Uo, const float* __restrict__ Vo, const float* __restrict__ bo,
                       float* __restrict__ out, long long out_size)
{
    __shared__ __align__(16) float hs0[HPF];
    __shared__ __align__(16) float2 xs[HALFSEQ];

    const int lane = threadIdx.x;
    const int bid  = blockIdx.x;
    const int half = (bid >= NUNIT) ? 1 : 0;
    const int u    = bid - half * NUNIT;
    const int j    = u >> 7;
    const int b    = u & 127;
    const int t0   = half * HALFSEQ;

    Params P;
    load_params(P, j, lane, Vi, Vf, Vc, Vo, Ui, Uf, Uc, Uo, bi, bf, bc, bo);

    const float* xq = x + (long long)b * SEQ * INSZ;
    float* outp = out + (long long)b * SEQ * HID + P.col + (long long)t0 * HID;

    // gather this half's x features into SMEM
    #pragma unroll 4
    for (int i = lane; i < HALFSEQ; i += 32) {
        xs[i] = make_float2(__ldg(xq + (t0 + i) * INSZ + P.fa),
                            __ldg(xq + (t0 + i) * INSZ + P.fb));
    }

    float h = 0.0f, c = 0.0f;
    if (half) {
        // wait for first-half producer, then load (h,c) at t=255
        if (lane == 0) {
            while (atomicAdd(&g_flag[u], 0) == 0) { __nanosleep(64); }
        }
        __syncwarp();
        __threadfence();
        h = __ldcg(&g_state[u * 64 + lane]);
        c = __ldcg(&g_state[u * 64 + 32 + lane]);
    }
    hs0[lane] = h;
    __syncwarp();

    for (int t = 0; t < HALFSEQ; ++t) {
        unsigned long long acc[4];
        matvec(acc, P, hs0, *reinterpret_cast<const unsigned long long*>(&xs[t]));
        gate_epilogue(acc, c, h);
        *outp = h; outp += HID;
        hs0[lane] = h;        // all h(t-1) reads precede this in program order
        __syncwarp();          // fence before next step's reads
    }

    if (!half) {
        // publish (h,c) for the second-half consumer
        g_state[u * 64 + lane]      = h;
        g_state[u * 64 + 32 + lane] = c;
        __threadfence();
        __syncwarp();
        if (lane == 0) atomicExch(&g_flag[u], 1);
    } else {
        // consume-reset so the next invocation starts clean
        __syncwarp();
        if (lane == 0) g_flag[u] = 0;
        const long long hsz = (long long)BATCHN * SEQ * HID;
        if (out_size >= hsz + 2LL * BATCHN * HID) {
            out[hsz + (long long)b * HID + P.col] = h;
            out[hsz + (long long)BATCHN * HID + (long long)b * HID + P.col] = c;
        }
    }
}

extern "C" void kernel_launch(void* const* d_in, const int* in_sizes, int n_in,
                              void* d_out, int out_size)
{
    const float* x  = (const float*)d_in[0];
    const float* Ui = (const float*)d_in[1];
    const float* Vi = (const float*)d_in[2];
    const float* bi = (const float*)d_in[3];
    const float* Uf = (const float*)d_in[4];
    const float* Vf = (const float*)d_in[5];
    const float* bf = (const float*)d_in[6];
    const float* Uc = (const float*)d_in[7];
    const float* Vc = (const float*)d_in[8];
    const float* bc = (const float*)d_in[9];
    const float* Uo = (const float*)d_in[10];
    const float* Vo = (const float*)d_in[11];
    const float* bo = (const float*)d_in[12];
    float* out = (float*)d_out;

    lstm_fused_kernel<<<NCTA, 32>>>(
        x, Ui, Vi, bi, Uf, Vf, bf, Uc, Vc, bc, Uo, Vo, bo,
        out, (long long)out_size);
}